// round 8
// baseline (speedup 1.0000x reference)
#include <cuda_runtime.h>
#include <cuda_bf16.h>
#include <cstdint>

// ---------------------------------------------------------------------------
// 2-layer GCN. CSR with packed (src, norm) edge records + split-bf16 mma.sync
// GEMMs (double-buffered cp.async), fused epilogues.
// ---------------------------------------------------------------------------

static constexpr int NNODES = 50000;
static constexpr int NEDGES = 800000;
static constexpr int INDIM  = 128;
static constexpr int ADDDIM = 8;
static constexpr int HID    = 256;
static constexpr int OUTD   = 128;

// -------------------- device scratch ----------------------------------------
__device__ __align__(16) __nv_bfloat16 g_aggx_hi[(size_t)NNODES * INDIM];
__device__ __align__(16) __nv_bfloat16 g_aggx_lo[(size_t)NNODES * INDIM];
__device__ __align__(16) __nv_bfloat16 g_h1_hi[(size_t)NNODES * HID];
__device__ __align__(16) __nv_bfloat16 g_h1_lo[(size_t)NNODES * HID];
__device__ __align__(16) float g_h2[(size_t)NNODES * OUTD];
__device__ float g_q[NNODES];
__device__ float g_dinv[NNODES];
__device__ int   g_deg[NNODES];
__device__ int   g_off[NNODES + 1];
__device__ int   g_cur[NNODES];
__device__ __align__(8) int2 g_edge[NEDGES];   // {src, norm_bits}
__device__ float g_c1[HID];
__device__ __align__(16) __nv_bfloat16 g_wt1_hi[HID * INDIM], g_wt1_lo[HID * INDIM];
__device__ __align__(16) __nv_bfloat16 g_wt2_hi[OUTD * HID],  g_wt2_lo[OUTD * HID];
__device__ int g_is64;

// -------------------- asm helpers -------------------------------------------
__device__ __forceinline__ uint32_t smem_u32(const void* p) {
    return (uint32_t)__cvta_generic_to_shared(p);
}
__device__ __forceinline__ void ldsm_x4(uint32_t r[4], uint32_t addr) {
    asm volatile("ldmatrix.sync.aligned.m8n8.x4.shared.b16 {%0,%1,%2,%3}, [%4];"
                 : "=r"(r[0]), "=r"(r[1]), "=r"(r[2]), "=r"(r[3]) : "r"(addr));
}
__device__ __forceinline__ void mma_bf16(float* c, const uint32_t* a,
                                         uint32_t b0, uint32_t b1) {
    asm volatile(
        "mma.sync.aligned.m16n8k16.row.col.f32.bf16.bf16.f32 "
        "{%0,%1,%2,%3}, {%4,%5,%6,%7}, {%8,%9}, {%0,%1,%2,%3};"
        : "+f"(c[0]), "+f"(c[1]), "+f"(c[2]), "+f"(c[3])
        : "r"(a[0]), "r"(a[1]), "r"(a[2]), "r"(a[3]), "r"(b0), "r"(b1));
}
__device__ __forceinline__ void cp16(uint32_t dst, const void* src, uint32_t sz) {
    asm volatile("cp.async.cg.shared.global [%0], [%1], 16, %2;"
                 :: "r"(dst), "l"(src), "r"(sz) : "memory");
}
__device__ __forceinline__ void cp_commit() {
    asm volatile("cp.async.commit_group;" ::: "memory");
}
template <int N>
__device__ __forceinline__ void cp_wait() {
    asm volatile("cp.async.wait_group %0;" :: "n"(N) : "memory");
}

// -------------------- prep kernels ------------------------------------------
__global__ void k_detect_zero(const long long* __restrict__ ei) {
    int i = blockIdx.x * blockDim.x + threadIdx.x;
    if (i < NNODES) g_deg[i] = 0;
    if (blockIdx.x == 0 && threadIdx.x < 32) {
        bool bad = false;
        for (int j = threadIdx.x; j < 512; j += 32) {
            long long v = ei[j];
            if (v < 0 || v >= NNODES) bad = true;
        }
        unsigned m = __ballot_sync(0xFFFFFFFFu, bad);
        if (threadIdx.x == 0) g_is64 = (m == 0u) ? 1 : 0;
    }
}
__global__ void k_deg(const void* __restrict__ ei) {
    int i = blockIdx.x * blockDim.x + threadIdx.x;       // pair index
    if (i >= NEDGES / 2) return;
    int d0, d1;
    if (g_is64) {
        longlong2 v = __ldg((const longlong2*)ei + NEDGES / 2 + i);
        d0 = (int)v.x; d1 = (int)v.y;
    } else {
        int2 v = __ldg((const int2*)ei + NEDGES / 2 + i);
        d0 = v.x; d1 = v.y;
    }
    atomicAdd(&g_deg[d0], 1);
    atomicAdd(&g_deg[d1], 1);
}
// exclusive scan; also writes dinv
__global__ void k_scan() {
    __shared__ int warpsum[32];
    __shared__ int chunk_total;
    const int t = threadIdx.x;               // 1024
    const int lane = t & 31, wid = t >> 5;
    int run = 0;
    for (int base = 0; base < NNODES; base += 2048) {
        int i0 = base + t * 2, i1 = i0 + 1;
        int v0 = (i0 < NNODES) ? g_deg[i0] : 0;
        int v1 = (i1 < NNODES) ? g_deg[i1] : 0;
        if (i0 < NNODES) g_dinv[i0] = rsqrtf((float)(v0 + 1));
        if (i1 < NNODES) g_dinv[i1] = rsqrtf((float)(v1 + 1));
        int v = v0 + v1;
        int x = v;
#pragma unroll
        for (int o = 1; o < 32; o <<= 1) {
            int y = __shfl_up_sync(0xFFFFFFFFu, x, o);
            if (lane >= o) x += y;
        }
        if (lane == 31) warpsum[wid] = x;
        __syncthreads();
        if (wid == 0) {
            int w = warpsum[lane];
#pragma unroll
            for (int o = 1; o < 32; o <<= 1) {
                int y = __shfl_up_sync(0xFFFFFFFFu, w, o);
                if (lane >= o) w += y;
            }
            warpsum[lane] = w;
            if (lane == 31) chunk_total = w;
        }
        __syncthreads();
        int excl = run + (wid ? warpsum[wid - 1] : 0) + x - v;
        if (i0 < NNODES) { g_off[i0] = excl; g_cur[i0] = excl; }
        if (i1 < NNODES) { g_off[i1] = excl + v0; g_cur[i1] = excl + v0; }
        run += chunk_total;
        __syncthreads();
    }
    if (t == 0) g_off[NNODES] = run;
}
// CSR fill with packed (src, norm) records
__global__ void k_csr(const void* __restrict__ ei) {
    int i = blockIdx.x * blockDim.x + threadIdx.x;       // pair index
    if (i >= NEDGES / 2) return;
    int s0, s1, d0, d1;
    if (g_is64) {
        longlong2 sv = __ldg((const longlong2*)ei + i);
        longlong2 dv = __ldg((const longlong2*)ei + NEDGES / 2 + i);
        s0 = (int)sv.x; s1 = (int)sv.y; d0 = (int)dv.x; d1 = (int)dv.y;
    } else {
        int2 sv = __ldg((const int2*)ei + i);
        int2 dv = __ldg((const int2*)ei + NEDGES / 2 + i);
        s0 = sv.x; s1 = sv.y; d0 = dv.x; d1 = dv.y;
    }
    float w0 = __ldg(&g_dinv[s0]) * __ldg(&g_dinv[d0]);
    float w1 = __ldg(&g_dinv[s1]) * __ldg(&g_dinv[d1]);
    int p0 = atomicAdd(&g_cur[d0], 1);
    g_edge[p0] = make_int2(s0, __float_as_int(w0));
    int p1 = atomicAdd(&g_cur[d1], 1);
    g_edge[p1] = make_int2(s1, __float_as_int(w1));
}
// fused: W1 split+transpose, W2 split+transpose, c1
__global__ void k_prepw(const float* __restrict__ W1, const float* __restrict__ W2,
                        const float* __restrict__ idv) {
    int idx = blockIdx.x * blockDim.x + threadIdx.x;
    constexpr int N1 = HID * INDIM;
    constexpr int N2 = OUTD * HID;
    if (idx < N1) {
        int o = idx / INDIM, i = idx % INDIM;
        float v = W1[(size_t)i * HID + o];
        __nv_bfloat16 h = __float2bfloat16_rn(v);
        g_wt1_hi[idx] = h;
        g_wt1_lo[idx] = __float2bfloat16_rn(v - __bfloat162float(h));
    } else if (idx < N1 + N2) {
        int j = idx - N1;
        int o = j / HID, i = j % HID;
        float v = W2[(size_t)i * OUTD + o];
        __nv_bfloat16 h = __float2bfloat16_rn(v);
        g_wt2_hi[j] = h;
        g_wt2_lo[j] = __float2bfloat16_rn(v - __bfloat162float(h));
    } else if (idx < N1 + N2 + HID) {
        int j = idx - N1 - N2;
        float s = 0.f;
#pragma unroll
        for (int t = 0; t < ADDDIM; t++) s += idv[t] * W1[(size_t)(INDIM + t) * HID + j];
        g_c1[j] = s;
    }
}

// -------------------- gather1: agg(x) -> bf16 hi/lo + q ---------------------
__global__ __launch_bounds__(256) void k_gather1(const float* __restrict__ x) {
    const int lane = threadIdx.x & 31;
    const int node = (blockIdx.x * blockDim.x + threadIdx.x) >> 5;
    if (node >= NNODES) return;
    const float dv = __ldg(&g_dinv[node]);
    const int e0 = __ldg(&g_off[node]), e1 = __ldg(&g_off[node + 1]);
    float4 acc = make_float4(0.f, 0.f, 0.f, 0.f);
    float q = 0.f;
    int e = e0;
    for (; e + 4 <= e1; e += 4) {
        int2 ev0 = __ldg(&g_edge[e]),     ev1 = __ldg(&g_edge[e + 1]);
        int2 ev2 = __ldg(&g_edge[e + 2]), ev3 = __ldg(&g_edge[e + 3]);
        float w0 = __int_as_float(ev0.y), w1 = __int_as_float(ev1.y);
        float w2 = __int_as_float(ev2.y), w3 = __int_as_float(ev3.y);
        q += (w0 + w1) + (w2 + w3);
        float4 v0 = __ldg((const float4*)(x + (size_t)ev0.x * INDIM) + lane);
        float4 v1 = __ldg((const float4*)(x + (size_t)ev1.x * INDIM) + lane);
        float4 v2 = __ldg((const float4*)(x + (size_t)ev2.x * INDIM) + lane);
        float4 v3 = __ldg((const float4*)(x + (size_t)ev3.x * INDIM) + lane);
        acc.x += v0.x * w0 + v1.x * w1 + v2.x * w2 + v3.x * w3;
        acc.y += v0.y * w0 + v1.y * w1 + v2.y * w2 + v3.y * w3;
        acc.z += v0.z * w0 + v1.z * w1 + v2.z * w2 + v3.z * w3;
        acc.w += v0.w * w0 + v1.w * w1 + v2.w * w2 + v3.w * w3;
    }
    for (; e < e1; e++) {
        int2 ev = __ldg(&g_edge[e]);
        float w0 = __int_as_float(ev.y);
        q += w0;
        float4 v0 = __ldg((const float4*)(x + (size_t)ev.x * INDIM) + lane);
        acc.x += v0.x * w0; acc.y += v0.y * w0;
        acc.z += v0.z * w0; acc.w += v0.w * w0;
    }
    {
        float w = dv * dv;
        q += w;
        float4 v = __ldg((const float4*)(x + (size_t)node * INDIM) + lane);
        acc.x += v.x * w; acc.y += v.y * w; acc.z += v.z * w; acc.w += v.w * w;
    }
    float vals[4] = {acc.x, acc.y, acc.z, acc.w};
    uint32_t hp[2], lp[2];
#pragma unroll
    for (int p = 0; p < 2; p++) {
        __nv_bfloat16 h0 = __float2bfloat16_rn(vals[p * 2]);
        __nv_bfloat16 h1 = __float2bfloat16_rn(vals[p * 2 + 1]);
        __nv_bfloat16 l0 = __float2bfloat16_rn(vals[p * 2] - __bfloat162float(h0));
        __nv_bfloat16 l1 = __float2bfloat16_rn(vals[p * 2 + 1] - __bfloat162float(h1));
        hp[p] = (uint32_t)__bfloat16_as_ushort(h0) | ((uint32_t)__bfloat16_as_ushort(h1) << 16);
        lp[p] = (uint32_t)__bfloat16_as_ushort(l0) | ((uint32_t)__bfloat16_as_ushort(l1) << 16);
    }
    size_t base = (size_t)node * INDIM + lane * 4;
    *(uint2*)&g_aggx_hi[base] = make_uint2(hp[0], hp[1]);
    *(uint2*)&g_aggx_lo[base] = make_uint2(lp[0], lp[1]);
    if (lane == 0) g_q[node] = q;
}

// -------------------- double-buffered split-bf16 GEMM -----------------------
template <int K, int NTOT, bool L1>
__global__ __launch_bounds__(256) void k_mma(
    const __nv_bfloat16* __restrict__ Ahi, const __nv_bfloat16* __restrict__ Alo,
    const __nv_bfloat16* __restrict__ Bhi, const __nv_bfloat16* __restrict__ Blo,
    const float* __restrict__ bias, const float* __restrict__ slope,
    __nv_bfloat16* __restrict__ OutHi, __nv_bfloat16* __restrict__ OutLo,
    float* __restrict__ OutF, int M) {
    constexpr int BK = 32, SA = 40;
    constexpr int NSEG = K / BK;
    constexpr int TILE = 128 * SA;

    extern __shared__ __align__(16) __nv_bfloat16 smem[];

    const int t = threadIdx.x;
    const int lane = t & 31, warp = t >> 5;
    const int wm0 = (warp >> 1) * 32;
    const int wn0 = (warp & 1) * 64;
    const int row0 = blockIdx.y * 128;
    const int n0 = blockIdx.x * 128;

    const int lr = t >> 1;
    const int lc = t & 1;

    const __nv_bfloat16* gsrc[4] = {Ahi, Alo, Bhi, Blo};

    auto load_seg = [&](int seg, int b) {
        const int k0 = seg * BK;
        const uint32_t sbase = smem_u32(smem) + (uint32_t)b * 4 * TILE * 2;
#pragma unroll
        for (int tl = 0; tl < 4; tl++) {
            const bool isA = (tl < 2);
            int grow = (isA ? row0 : n0) + lr;
            const __nv_bfloat16* gp = gsrc[tl] + (size_t)grow * K + k0;
            uint32_t dst = sbase + (uint32_t)(tl * TILE + lr * SA) * 2;
            uint32_t ok = (!isA || grow < M) ? 16u : 0u;
#pragma unroll
            for (int c = 0; c < 2; c++) {
                int ch = lc + c * 2;
                cp16(dst + ch * 16, gp + ch * 8, ok);
            }
        }
        cp_commit();
    };

    float acc[2][8][4] = {};

    load_seg(0, 0);
    for (int s = 0; s < NSEG; s++) {
        const int b = s & 1;
        if (s + 1 < NSEG) load_seg(s + 1, b ^ 1);
        if (s + 1 < NSEG) cp_wait<1>(); else cp_wait<0>();
        __syncthreads();

        const uint32_t sb = smem_u32(smem) + (uint32_t)b * 4 * TILE * 2;
        const uint32_t aHi = sb, aLo = sb + TILE * 2;
        const uint32_t bHi = sb + 2 * TILE * 2, bLo = sb + 3 * TILE * 2;

#pragma unroll
        for (int ph = 0; ph < 3; ph++) {
            const uint32_t at = (ph == 1) ? aLo : aHi;
            const uint32_t bt = (ph == 2) ? bLo : bHi;
#pragma unroll
            for (int kh = 0; kh < 2; kh++) {
                uint32_t af[2][4], bf[4][4];
#pragma unroll
                for (int mi = 0; mi < 2; mi++) {
                    uint32_t addr = at +
                        ((wm0 + mi * 16 + (lane & 15)) * SA + kh * 16 + (lane >> 4) * 8) * 2;
                    ldsm_x4(af[mi], addr);
                }
#pragma unroll
                for (int nq = 0; nq < 4; nq++) {
                    uint32_t addr = bt +
                        ((wn0 + nq * 16 + (lane & 7) + ((lane >> 4) & 1) * 8) * SA +
                         kh * 16 + ((lane >> 3) & 1) * 8) * 2;
                    ldsm_x4(bf[nq], addr);
                }
#pragma unroll
                for (int mi = 0; mi < 2; mi++)
#pragma unroll
                    for (int nq = 0; nq < 4; nq++) {
                        mma_bf16(acc[mi][nq * 2],     af[mi], bf[nq][0], bf[nq][1]);
                        mma_bf16(acc[mi][nq * 2 + 1], af[mi], bf[nq][2], bf[nq][3]);
                    }
            }
        }
        __syncthreads();
    }

    // epilogue
    float qv[2][2];
    if (L1) {
#pragma unroll
        for (int mi = 0; mi < 2; mi++) {
            int r0 = row0 + wm0 + mi * 16 + (lane >> 2);
            qv[mi][0] = (r0 < M) ? __ldg(&g_q[r0]) : 0.f;
            qv[mi][1] = (r0 + 8 < M) ? __ldg(&g_q[r0 + 8]) : 0.f;
        }
    }
#pragma unroll
    for (int mi = 0; mi < 2; mi++) {
        int r0 = row0 + wm0 + mi * 16 + (lane >> 2);
#pragma unroll
        for (int nt = 0; nt < 8; nt++) {
            int c0 = n0 + wn0 + nt * 8 + (lane & 3) * 2;
            if (L1) {
                float cc0 = __ldg(&g_c1[c0]),   cc1 = __ldg(&g_c1[c0 + 1]);
                float bb0 = __ldg(&bias[c0]),   bb1 = __ldg(&bias[c0 + 1]);
                float ss0 = __ldg(&slope[c0]),  ss1 = __ldg(&slope[c0 + 1]);
#pragma unroll
                for (int h = 0; h < 2; h++) {
                    int r = r0 + h * 8;
                    if (r >= M) continue;
                    float v0 = acc[mi][nt][h * 2]     + qv[mi][h] * cc0 + bb0;
                    float v1 = acc[mi][nt][h * 2 + 1] + qv[mi][h] * cc1 + bb1;
                    v0 = v0 >= 0.f ? v0 : ss0 * v0;
                    v1 = v1 >= 0.f ? v1 : ss1 * v1;
                    __nv_bfloat16 h0 = __float2bfloat16_rn(v0);
                    __nv_bfloat16 h1 = __float2bfloat16_rn(v1);
                    __nv_bfloat16 l0 = __float2bfloat16_rn(v0 - __bfloat162float(h0));
                    __nv_bfloat16 l1 = __float2bfloat16_rn(v1 - __bfloat162float(h1));
                    size_t o = (size_t)r * NTOT + c0;
                    *(uint32_t*)(OutHi + o) = (uint32_t)__bfloat16_as_ushort(h0) |
                                              ((uint32_t)__bfloat16_as_ushort(h1) << 16);
                    *(uint32_t*)(OutLo + o) = (uint32_t)__bfloat16_as_ushort(l0) |
                                              ((uint32_t)__bfloat16_as_ushort(l1) << 16);
                }
            } else {
#pragma unroll
                for (int h = 0; h < 2; h++) {
                    int r = r0 + h * 8;
                    if (r >= M) continue;
                    *(float2*)(OutF + (size_t)r * NTOT + c0) =
                        make_float2(acc[mi][nt][h * 2], acc[mi][nt][h * 2 + 1]);
                }
            }
        }
    }
}

// -------------------- gather2: 128-dim, fused bias+prelu --------------------
__global__ __launch_bounds__(256) void k_gather2(const float* __restrict__ bias,
                                                 const float* __restrict__ slope,
                                                 float* __restrict__ out) {
    const int lane = threadIdx.x & 31;
    const int node = (blockIdx.x * blockDim.x + threadIdx.x) >> 5;
    if (node >= NNODES) return;
    const float dv = __ldg(&g_dinv[node]);
    const int e0 = __ldg(&g_off[node]), e1 = __ldg(&g_off[node + 1]);
    float4 acc = make_float4(0.f, 0.f, 0.f, 0.f);
    const float* h = g_h2;
    int e = e0;
    for (; e + 4 <= e1; e += 4) {
        int2 ev0 = __ldg(&g_edge[e]),     ev1 = __ldg(&g_edge[e + 1]);
        int2 ev2 = __ldg(&g_edge[e + 2]), ev3 = __ldg(&g_edge[e + 3]);
        float w0 = __int_as_float(ev0.y), w1 = __int_as_float(ev1.y);
        float w2 = __int_as_float(ev2.y), w3 = __int_as_float(ev3.y);
        float4 v0 = __ldg((const float4*)(h + (size_t)ev0.x * OUTD) + lane);
        float4 v1 = __ldg((const float4*)(h + (size_t)ev1.x * OUTD) + lane);
        float4 v2 = __ldg((const float4*)(h + (size_t)ev2.x * OUTD) + lane);
        float4 v3 = __ldg((const float4*)(h + (size_t)ev3.x * OUTD) + lane);
        acc.x += v0.x * w0 + v1.x * w1 + v2.x * w2 + v3.x * w3;
        acc.y += v0.y * w0 + v1.y * w1 + v2.y * w2 + v3.y * w3;
        acc.z += v0.z * w0 + v1.z * w1 + v2.z * w2 + v3.z * w3;
        acc.w += v0.w * w0 + v1.w * w1 + v2.w * w2 + v3.w * w3;
    }
    for (; e < e1; e++) {
        int2 ev = __ldg(&g_edge[e]);
        float w0 = __int_as_float(ev.y);
        float4 v0 = __ldg((const float4*)(h + (size_t)ev.x * OUTD) + lane);
        acc.x += v0.x * w0; acc.y += v0.y * w0;
        acc.z += v0.z * w0; acc.w += v0.w * w0;
    }
    {
        float w = dv * dv;
        float4 v = __ldg((const float4*)(h + (size_t)node * OUTD) + lane);
        acc.x += v.x * w; acc.y += v.y * w; acc.z += v.z * w; acc.w += v.w * w;
    }
    float4 B = *(const float4*)&bias[lane * 4];
    float4 S = *(const float4*)&slope[lane * 4];
    float r0 = acc.x + B.x, r1 = acc.y + B.y, r2 = acc.z + B.z, r3 = acc.w + B.w;
    float4 o;
    o.x = r0 >= 0.f ? r0 : S.x * r0;
    o.y = r1 >= 0.f ? r1 : S.y * r1;
    o.z = r2 >= 0.f ? r2 : S.z * r2;
    o.w = r3 >= 0.f ? r3 : S.w * r3;
    *(float4*)&out[(size_t)node * OUTD + lane * 4] = o;
}

// -------------------- launch ------------------------------------------------
extern "C" void kernel_launch(void* const* d_in, const int* in_sizes, int n_in,
                              void* d_out, int out_size) {
    const float* x  = (const float*)d_in[0];
    const void*  ei = d_in[1];
    const float* idv = (const float*)d_in[2];
    const float* W1 = (const float*)d_in[3];
    const float* b1 = (const float*)d_in[4];
    const float* a1 = (const float*)d_in[5];
    const float* W2 = (const float*)d_in[6];
    const float* b2 = (const float*)d_in[7];
    const float* a2 = (const float*)d_in[8];
    float* out = (float*)d_out;

    __nv_bfloat16 *d_axh, *d_axl, *d_h1h, *d_h1l, *d_w1h, *d_w1l, *d_w2h, *d_w2l;
    float *d_h2;
    cudaGetSymbolAddress((void**)&d_axh, g_aggx_hi);
    cudaGetSymbolAddress((void**)&d_axl, g_aggx_lo);
    cudaGetSymbolAddress((void**)&d_h1h, g_h1_hi);
    cudaGetSymbolAddress((void**)&d_h1l, g_h1_lo);
    cudaGetSymbolAddress((void**)&d_w1h, g_wt1_hi);
    cudaGetSymbolAddress((void**)&d_w1l, g_wt1_lo);
    cudaGetSymbolAddress((void**)&d_w2h, g_wt2_hi);
    cudaGetSymbolAddress((void**)&d_w2l, g_wt2_lo);
    cudaGetSymbolAddress((void**)&d_h2, g_h2);

    const int T = 256;
    constexpr int SMEM_MMA = 2 * 4 * 128 * 40 * 2;   // 81920 B

    static bool attr_done = false;
    if (!attr_done) {
        cudaFuncSetAttribute(k_mma<INDIM, HID, true>,
                             cudaFuncAttributeMaxDynamicSharedMemorySize, SMEM_MMA);
        cudaFuncSetAttribute(k_mma<HID, OUTD, false>,
                             cudaFuncAttributeMaxDynamicSharedMemorySize, SMEM_MMA);
        attr_done = true;
    }

    k_detect_zero<<<(NNODES + T - 1) / T, T>>>((const long long*)ei);
    k_deg<<<(NEDGES / 2 + T - 1) / T, T>>>(ei);
    k_scan<<<1, 1024>>>();
    k_csr<<<(NEDGES / 2 + T - 1) / T, T>>>(ei);
    k_prepw<<<(HID * INDIM + OUTD * HID + HID + T - 1) / T, T>>>(W1, W2, idv);

    k_gather1<<<(NNODES * 32 + T - 1) / T, T>>>(x);

    {   // GEMM1
        dim3 grid(HID / 128, (NNODES + 127) / 128);
        k_mma<INDIM, HID, true><<<grid, 256, SMEM_MMA>>>(
            d_axh, d_axl, d_w1h, d_w1l, b1, a1, d_h1h, d_h1l, nullptr, NNODES);
    }
    {   // GEMM2
        dim3 grid(OUTD / 128, (NNODES + 127) / 128);
        k_mma<HID, OUTD, false><<<grid, 256, SMEM_MMA>>>(
            d_h1h, d_h1l, d_w2h, d_w2l, nullptr, nullptr, nullptr, nullptr,
            d_h2, NNODES);
    }
    k_gather2<<<(NNODES * 32 + T - 1) / T, T>>>(b2, a2, out);
}

// round 9
// speedup vs baseline: 1.4982x; 1.4982x over previous
#include <cuda_runtime.h>
#include <cuda_bf16.h>
#include <cstdint>

// ---------------------------------------------------------------------------
// 2-layer GCN. CSR gather + split-bf16 mma.sync GEMMs (double-buffered cp.async)
// R9 = R6 baseline + GEMM2 with 128x64 CTA tile (3 CTAs/SM, better waves).
// ---------------------------------------------------------------------------

static constexpr int NNODES = 50000;
static constexpr int NEDGES = 800000;
static constexpr int INDIM  = 128;
static constexpr int ADDDIM = 8;
static constexpr int HID    = 256;
static constexpr int OUTD   = 128;

// -------------------- device scratch ----------------------------------------
__device__ __align__(16) __nv_bfloat16 g_aggx_hi[(size_t)NNODES * INDIM];
__device__ __align__(16) __nv_bfloat16 g_aggx_lo[(size_t)NNODES * INDIM];
__device__ __align__(16) __nv_bfloat16 g_h1_hi[(size_t)NNODES * HID];
__device__ __align__(16) __nv_bfloat16 g_h1_lo[(size_t)NNODES * HID];
__device__ __align__(16) float g_h2[(size_t)NNODES * OUTD];
__device__ float g_q[NNODES];
__device__ float g_dinv[NNODES];
__device__ int   g_deg[NNODES];
__device__ int   g_off[NNODES + 1];
__device__ int   g_cur[NNODES];
__device__ int   g_src[NEDGES];
__device__ float g_c1[HID];
__device__ __align__(16) __nv_bfloat16 g_wt1_hi[HID * INDIM], g_wt1_lo[HID * INDIM];
__device__ __align__(16) __nv_bfloat16 g_wt2_hi[OUTD * HID],  g_wt2_lo[OUTD * HID];
__device__ int g_is64;

// -------------------- asm helpers -------------------------------------------
__device__ __forceinline__ uint32_t smem_u32(const void* p) {
    return (uint32_t)__cvta_generic_to_shared(p);
}
__device__ __forceinline__ void ldsm_x4(uint32_t r[4], uint32_t addr) {
    asm volatile("ldmatrix.sync.aligned.m8n8.x4.shared.b16 {%0,%1,%2,%3}, [%4];"
                 : "=r"(r[0]), "=r"(r[1]), "=r"(r[2]), "=r"(r[3]) : "r"(addr));
}
__device__ __forceinline__ void mma_bf16(float* c, const uint32_t* a,
                                         uint32_t b0, uint32_t b1) {
    asm volatile(
        "mma.sync.aligned.m16n8k16.row.col.f32.bf16.bf16.f32 "
        "{%0,%1,%2,%3}, {%4,%5,%6,%7}, {%8,%9}, {%0,%1,%2,%3};"
        : "+f"(c[0]), "+f"(c[1]), "+f"(c[2]), "+f"(c[3])
        : "r"(a[0]), "r"(a[1]), "r"(a[2]), "r"(a[3]), "r"(b0), "r"(b1));
}
__device__ __forceinline__ void cp16(uint32_t dst, const void* src, uint32_t sz) {
    asm volatile("cp.async.cg.shared.global [%0], [%1], 16, %2;"
                 :: "r"(dst), "l"(src), "r"(sz) : "memory");
}
__device__ __forceinline__ void cp_commit() {
    asm volatile("cp.async.commit_group;" ::: "memory");
}
template <int N>
__device__ __forceinline__ void cp_wait() {
    asm volatile("cp.async.wait_group %0;" :: "n"(N) : "memory");
}

// -------------------- prep kernels ------------------------------------------
__global__ void k_detect_zero(const long long* __restrict__ ei) {
    int i = blockIdx.x * blockDim.x + threadIdx.x;
    if (i < NNODES) g_deg[i] = 0;
    if (blockIdx.x == 0 && threadIdx.x < 32) {
        bool bad = false;
        for (int j = threadIdx.x; j < 512; j += 32) {
            long long v = ei[j];
            if (v < 0 || v >= NNODES) bad = true;
        }
        unsigned m = __ballot_sync(0xFFFFFFFFu, bad);
        if (threadIdx.x == 0) g_is64 = (m == 0u) ? 1 : 0;
    }
}
__global__ void k_deg(const void* __restrict__ ei) {
    int i = blockIdx.x * blockDim.x + threadIdx.x;       // pair index
    if (i >= NEDGES / 2) return;
    int d0, d1;
    if (g_is64) {
        longlong2 v = __ldg((const longlong2*)ei + NEDGES / 2 + i);
        d0 = (int)v.x; d1 = (int)v.y;
    } else {
        int2 v = __ldg((const int2*)ei + NEDGES / 2 + i);
        d0 = v.x; d1 = v.y;
    }
    atomicAdd(&g_deg[d0], 1);
    atomicAdd(&g_deg[d1], 1);
}
// exclusive scan (2 elems/thread); also writes dinv
__global__ void k_scan() {
    __shared__ int warpsum[32];
    __shared__ int chunk_total;
    const int t = threadIdx.x;               // 1024
    const int lane = t & 31, wid = t >> 5;
    int run = 0;
    for (int base = 0; base < NNODES; base += 2048) {
        int i0 = base + t * 2, i1 = i0 + 1;
        int v0 = (i0 < NNODES) ? g_deg[i0] : 0;
        int v1 = (i1 < NNODES) ? g_deg[i1] : 0;
        if (i0 < NNODES) g_dinv[i0] = rsqrtf((float)(v0 + 1));
        if (i1 < NNODES) g_dinv[i1] = rsqrtf((float)(v1 + 1));
        int v = v0 + v1;
        int x = v;
#pragma unroll
        for (int o = 1; o < 32; o <<= 1) {
            int y = __shfl_up_sync(0xFFFFFFFFu, x, o);
            if (lane >= o) x += y;
        }
        if (lane == 31) warpsum[wid] = x;
        __syncthreads();
        if (wid == 0) {
            int w = warpsum[lane];
#pragma unroll
            for (int o = 1; o < 32; o <<= 1) {
                int y = __shfl_up_sync(0xFFFFFFFFu, w, o);
                if (lane >= o) w += y;
            }
            warpsum[lane] = w;
            if (lane == 31) chunk_total = w;
        }
        __syncthreads();
        int excl = run + (wid ? warpsum[wid - 1] : 0) + x - v;
        if (i0 < NNODES) { g_off[i0] = excl; g_cur[i0] = excl; }
        if (i1 < NNODES) { g_off[i1] = excl + v0; g_cur[i1] = excl + v0; }
        run += chunk_total;
        __syncthreads();
    }
    if (t == 0) g_off[NNODES] = run;
}
__global__ void k_csr(const void* __restrict__ ei) {
    int i = blockIdx.x * blockDim.x + threadIdx.x;       // pair index
    if (i >= NEDGES / 2) return;
    int s0, s1, d0, d1;
    if (g_is64) {
        longlong2 sv = __ldg((const longlong2*)ei + i);
        longlong2 dv = __ldg((const longlong2*)ei + NEDGES / 2 + i);
        s0 = (int)sv.x; s1 = (int)sv.y; d0 = (int)dv.x; d1 = (int)dv.y;
    } else {
        int2 sv = __ldg((const int2*)ei + i);
        int2 dv = __ldg((const int2*)ei + NEDGES / 2 + i);
        s0 = sv.x; s1 = sv.y; d0 = dv.x; d1 = dv.y;
    }
    int p0 = atomicAdd(&g_cur[d0], 1);
    g_src[p0] = s0;
    int p1 = atomicAdd(&g_cur[d1], 1);
    g_src[p1] = s1;
}
// fused: W1 split+transpose, W2 split+transpose, c1
__global__ void k_prepw(const float* __restrict__ W1, const float* __restrict__ W2,
                        const float* __restrict__ idv) {
    int idx = blockIdx.x * blockDim.x + threadIdx.x;
    constexpr int N1 = HID * INDIM;
    constexpr int N2 = OUTD * HID;
    if (idx < N1) {
        int o = idx / INDIM, i = idx % INDIM;
        float v = W1[(size_t)i * HID + o];
        __nv_bfloat16 h = __float2bfloat16_rn(v);
        g_wt1_hi[idx] = h;
        g_wt1_lo[idx] = __float2bfloat16_rn(v - __bfloat162float(h));
    } else if (idx < N1 + N2) {
        int j = idx - N1;
        int o = j / HID, i = j % HID;
        float v = W2[(size_t)i * OUTD + o];
        __nv_bfloat16 h = __float2bfloat16_rn(v);
        g_wt2_hi[j] = h;
        g_wt2_lo[j] = __float2bfloat16_rn(v - __bfloat162float(h));
    } else if (idx < N1 + N2 + HID) {
        int j = idx - N1 - N2;
        float s = 0.f;
#pragma unroll
        for (int t = 0; t < ADDDIM; t++) s += idv[t] * W1[(size_t)(INDIM + t) * HID + j];
        g_c1[j] = s;
    }
}

// -------------------- gather1: agg(x) -> bf16 hi/lo + q ---------------------
__global__ __launch_bounds__(256) void k_gather1(const float* __restrict__ x) {
    const int lane = threadIdx.x & 31;
    const int node = (blockIdx.x * blockDim.x + threadIdx.x) >> 5;
    if (node >= NNODES) return;
    const float dv = g_dinv[node];
    const int e0 = g_off[node], e1 = g_off[node + 1];
    float4 acc = make_float4(0.f, 0.f, 0.f, 0.f);
    float q = 0.f;
    int e = e0;
    for (; e + 4 <= e1; e += 4) {
        int s0 = __ldg(&g_src[e]),     s1 = __ldg(&g_src[e + 1]);
        int s2 = __ldg(&g_src[e + 2]), s3 = __ldg(&g_src[e + 3]);
        float w0 = __ldg(&g_dinv[s0]) * dv, w1 = __ldg(&g_dinv[s1]) * dv;
        float w2 = __ldg(&g_dinv[s2]) * dv, w3 = __ldg(&g_dinv[s3]) * dv;
        q += (w0 + w1) + (w2 + w3);
        float4 v0 = __ldg((const float4*)(x + (size_t)s0 * INDIM) + lane);
        float4 v1 = __ldg((const float4*)(x + (size_t)s1 * INDIM) + lane);
        float4 v2 = __ldg((const float4*)(x + (size_t)s2 * INDIM) + lane);
        float4 v3 = __ldg((const float4*)(x + (size_t)s3 * INDIM) + lane);
        acc.x += v0.x * w0 + v1.x * w1 + v2.x * w2 + v3.x * w3;
        acc.y += v0.y * w0 + v1.y * w1 + v2.y * w2 + v3.y * w3;
        acc.z += v0.z * w0 + v1.z * w1 + v2.z * w2 + v3.z * w3;
        acc.w += v0.w * w0 + v1.w * w1 + v2.w * w2 + v3.w * w3;
    }
    for (; e < e1; e++) {
        int s0 = __ldg(&g_src[e]);
        float w0 = __ldg(&g_dinv[s0]) * dv;
        q += w0;
        float4 v0 = __ldg((const float4*)(x + (size_t)s0 * INDIM) + lane);
        acc.x += v0.x * w0; acc.y += v0.y * w0;
        acc.z += v0.z * w0; acc.w += v0.w * w0;
    }
    {
        float w = dv * dv;
        q += w;
        float4 v = __ldg((const float4*)(x + (size_t)node * INDIM) + lane);
        acc.x += v.x * w; acc.y += v.y * w; acc.z += v.z * w; acc.w += v.w * w;
    }
    float vals[4] = {acc.x, acc.y, acc.z, acc.w};
    uint32_t hp[2], lp[2];
#pragma unroll
    for (int p = 0; p < 2; p++) {
        __nv_bfloat16 h0 = __float2bfloat16_rn(vals[p * 2]);
        __nv_bfloat16 h1 = __float2bfloat16_rn(vals[p * 2 + 1]);
        __nv_bfloat16 l0 = __float2bfloat16_rn(vals[p * 2] - __bfloat162float(h0));
        __nv_bfloat16 l1 = __float2bfloat16_rn(vals[p * 2 + 1] - __bfloat162float(h1));
        hp[p] = (uint32_t)__bfloat16_as_ushort(h0) | ((uint32_t)__bfloat16_as_ushort(h1) << 16);
        lp[p] = (uint32_t)__bfloat16_as_ushort(l0) | ((uint32_t)__bfloat16_as_ushort(l1) << 16);
    }
    size_t base = (size_t)node * INDIM + lane * 4;
    *(uint2*)&g_aggx_hi[base] = make_uint2(hp[0], hp[1]);
    *(uint2*)&g_aggx_lo[base] = make_uint2(lp[0], lp[1]);
    if (lane == 0) g_q[node] = q;
}

// -------------------- double-buffered split-bf16 GEMM -----------------------
// CTA tile: 128 rows x BN cols. 8 warps in 4x2 (warp tile 32 x BN/2). BK=32.
// smem per buffer: Ahi,Alo (128xSA) + Bhi,Blo (BNxSA).
template <int K, int NTOT, int BN, bool L1>
__global__ __launch_bounds__(256) void k_mma(
    const __nv_bfloat16* __restrict__ Ahi, const __nv_bfloat16* __restrict__ Alo,
    const __nv_bfloat16* __restrict__ Bhi, const __nv_bfloat16* __restrict__ Blo,
    const float* __restrict__ bias, const float* __restrict__ slope,
    __nv_bfloat16* __restrict__ OutHi, __nv_bfloat16* __restrict__ OutLo,
    float* __restrict__ OutF, int M) {
    constexpr int BK = 32, SA = 40;
    constexpr int NSEG = K / BK;
    constexpr int TA = 128 * SA * 2;            // A tile bytes
    constexpr int TB = BN * SA * 2;             // B tile bytes
    constexpr int BUF = 2 * TA + 2 * TB;        // bytes per buffer
    constexpr int NQ = BN / 32;                 // 16-col groups per warp

    extern __shared__ __align__(16) __nv_bfloat16 smem[];

    const int t = threadIdx.x;
    const int lane = t & 31, warp = t >> 5;
    const int wm0 = (warp >> 1) * 32;
    const int wn0 = (warp & 1) * (BN / 2);
    const int row0 = blockIdx.y * 128;
    const int n0 = blockIdx.x * BN;

    auto load_seg = [&](int seg, int b) {
        const int k0 = seg * BK;
        const uint32_t sbase = smem_u32(smem) + (uint32_t)b * BUF;
        // A tiles: 128 rows x 4 chunks(16B) = 512 chunks each
#pragma unroll
        for (int tl = 0; tl < 2; tl++) {
            const __nv_bfloat16* G = tl ? Alo : Ahi;
            uint32_t tbase = sbase + tl * TA;
#pragma unroll
            for (int c = t; c < 512; c += 256) {
                int r = c >> 2, ch = c & 3;
                int gr = row0 + r;
                uint32_t ok = (gr < M) ? 16u : 0u;
                cp16(tbase + r * (SA * 2) + ch * 16,
                     G + (size_t)gr * K + k0 + ch * 8, ok);
            }
        }
        // B tiles: BN rows x 4 chunks
#pragma unroll
        for (int tl = 0; tl < 2; tl++) {
            const __nv_bfloat16* G = tl ? Blo : Bhi;
            uint32_t tbase = sbase + 2 * TA + tl * TB;
#pragma unroll
            for (int c = t; c < BN * 4; c += 256) {
                int r = c >> 2, ch = c & 3;
                cp16(tbase + r * (SA * 2) + ch * 16,
                     G + (size_t)(n0 + r) * K + k0 + ch * 8, 16u);
            }
        }
        cp_commit();
    };

    float acc[2][2 * NQ][4] = {};

    load_seg(0, 0);
    for (int s = 0; s < NSEG; s++) {
        const int b = s & 1;
        if (s + 1 < NSEG) load_seg(s + 1, b ^ 1);
        if (s + 1 < NSEG) cp_wait<1>(); else cp_wait<0>();
        __syncthreads();

        const uint32_t sb = smem_u32(smem) + (uint32_t)b * BUF;
        const uint32_t aHi = sb, aLo = sb + TA;
        const uint32_t bHi = sb + 2 * TA, bLo = sb + 2 * TA + TB;

#pragma unroll
        for (int ph = 0; ph < 3; ph++) {
            const uint32_t at = (ph == 1) ? aLo : aHi;
            const uint32_t bt = (ph == 2) ? bLo : bHi;
#pragma unroll
            for (int kh = 0; kh < 2; kh++) {
                uint32_t af[2][4], bf[NQ][4];
#pragma unroll
                for (int mi = 0; mi < 2; mi++) {
                    uint32_t addr = at +
                        ((wm0 + mi * 16 + (lane & 15)) * SA + kh * 16 + (lane >> 4) * 8) * 2;
                    ldsm_x4(af[mi], addr);
                }
#pragma unroll
                for (int nq = 0; nq < NQ; nq++) {
                    uint32_t addr = bt +
                        ((wn0 + nq * 16 + (lane & 7) + ((lane >> 4) & 1) * 8) * SA +
                         kh * 16 + ((lane >> 3) & 1) * 8) * 2;
                    ldsm_x4(bf[nq], addr);
                }
#pragma unroll
                for (int mi = 0; mi < 2; mi++)
#pragma unroll
                    for (int nq = 0; nq < NQ; nq++) {
                        mma_bf16(acc[mi][nq * 2],     af[mi], bf[nq][0], bf[nq][1]);
                        mma_bf16(acc[mi][nq * 2 + 1], af[mi], bf[nq][2], bf[nq][3]);
                    }
            }
        }
        __syncthreads();
    }

    // epilogue
    float qv[2][2];
    if (L1) {
#pragma unroll
        for (int mi = 0; mi < 2; mi++) {
            int r0 = row0 + wm0 + mi * 16 + (lane >> 2);
            qv[mi][0] = (r0 < M) ? __ldg(&g_q[r0]) : 0.f;
            qv[mi][1] = (r0 + 8 < M) ? __ldg(&g_q[r0 + 8]) : 0.f;
        }
    }
#pragma unroll
    for (int mi = 0; mi < 2; mi++) {
        int r0 = row0 + wm0 + mi * 16 + (lane >> 2);
#pragma unroll
        for (int nt = 0; nt < 2 * NQ; nt++) {
            int c0 = n0 + wn0 + nt * 8 + (lane & 3) * 2;
            if (L1) {
                float cc0 = __ldg(&g_c1[c0]),   cc1 = __ldg(&g_c1[c0 + 1]);
                float bb0 = __ldg(&bias[c0]),   bb1 = __ldg(&bias[c0 + 1]);
                float ss0 = __ldg(&slope[c0]),  ss1 = __ldg(&slope[c0 + 1]);
#pragma unroll
                for (int h = 0; h < 2; h++) {
                    int r = r0 + h * 8;
                    if (r >= M) continue;
                    float v0 = acc[mi][nt][h * 2]     + qv[mi][h] * cc0 + bb0;
                    float v1 = acc[mi][nt][h * 2 + 1] + qv[mi][h] * cc1 + bb1;
                    v0 = v0 >= 0.f ? v0 : ss0 * v0;
                    v1 = v1 >= 0.f ? v1 : ss1 * v1;
                    __nv_bfloat16 h0 = __float2bfloat16_rn(v0);
                    __nv_bfloat16 h1 = __float2bfloat16_rn(v1);
                    __nv_bfloat16 l0 = __float2bfloat16_rn(v0 - __bfloat162float(h0));
                    __nv_bfloat16 l1 = __float2bfloat16_rn(v1 - __bfloat162float(h1));
                    size_t o = (size_t)r * NTOT + c0;
                    *(uint32_t*)(OutHi + o) = (uint32_t)__bfloat16_as_ushort(h0) |
                                              ((uint32_t)__bfloat16_as_ushort(h1) << 16);
                    *(uint32_t*)(OutLo + o) = (uint32_t)__bfloat16_as_ushort(l0) |
                                              ((uint32_t)__bfloat16_as_ushort(l1) << 16);
                }
            } else {
#pragma unroll
                for (int h = 0; h < 2; h++) {
                    int r = r0 + h * 8;
                    if (r >= M) continue;
                    *(float2*)(OutF + (size_t)r * NTOT + c0) =
                        make_float2(acc[mi][nt][h * 2], acc[mi][nt][h * 2 + 1]);
                }
            }
        }
    }
}

// -------------------- gather2: 128-dim, fused bias+prelu --------------------
__global__ __launch_bounds__(256) void k_gather2(const float* __restrict__ bias,
                                                 const float* __restrict__ slope,
                                                 float* __restrict__ out) {
    const int lane = threadIdx.x & 31;
    const int node = (blockIdx.x * blockDim.x + threadIdx.x) >> 5;
    if (node >= NNODES) return;
    const float dv = g_dinv[node];
    const int e0 = g_off[node], e1 = g_off[node + 1];
    float4 acc = make_float4(0.f, 0.f, 0.f, 0.f);
    const float* h = g_h2;
    int e = e0;
    for (; e + 4 <= e1; e += 4) {
        int s0 = __ldg(&g_src[e]),     s1 = __ldg(&g_src[e + 1]);
        int s2 = __ldg(&g_src[e + 2]), s3 = __ldg(&g_src[e + 3]);
        float w0 = __ldg(&g_dinv[s0]) * dv, w1 = __ldg(&g_dinv[s1]) * dv;
        float w2 = __ldg(&g_dinv[s2]) * dv, w3 = __ldg(&g_dinv[s3]) * dv;
        float4 v0 = __ldg((const float4*)(h + (size_t)s0 * OUTD) + lane);
        float4 v1 = __ldg((const float4*)(h + (size_t)s1 * OUTD) + lane);
        float4 v2 = __ldg((const float4*)(h + (size_t)s2 * OUTD) + lane);
        float4 v3 = __ldg((const float4*)(h + (size_t)s3 * OUTD) + lane);
        acc.x += v0.x * w0 + v1.x * w1 + v2.x * w2 + v3.x * w3;
        acc.y += v0.y * w0 + v1.y * w1 + v2.y * w2 + v3.y * w3;
        acc.z += v0.z * w0 + v1.z * w1 + v2.z * w2 + v3.z * w3;
        acc.w += v0.w * w0 + v1.w * w1 + v2.w * w2 + v3.w * w3;
    }
    for (; e < e1; e++) {
        int s0 = __ldg(&g_src[e]);
        float w0 = __ldg(&g_dinv[s0]) * dv;
        float4 v0 = __ldg((const float4*)(h + (size_t)s0 * OUTD) + lane);
        acc.x += v0.x * w0; acc.y += v0.y * w0;
        acc.z += v0.z * w0; acc.w += v0.w * w0;
    }
    {
        float w = dv * dv;
        float4 v = __ldg((const float4*)(h + (size_t)node * OUTD) + lane);
        acc.x += v.x * w; acc.y += v.y * w; acc.z += v.z * w; acc.w += v.w * w;
    }
    float4 B = *(const float4*)&bias[lane * 4];
    float4 S = *(const float4*)&slope[lane * 4];
    float r0 = acc.x + B.x, r1 = acc.y + B.y, r2 = acc.z + B.z, r3 = acc.w + B.w;
    float4 o;
    o.x = r0 >= 0.f ? r0 : S.x * r0;
    o.y = r1 >= 0.f ? r1 : S.y * r1;
    o.z = r2 >= 0.f ? r2 : S.z * r2;
    o.w = r3 >= 0.f ? r3 : S.w * r3;
    *(float4*)&out[(size_t)node * OUTD + lane * 4] = o;
}

// -------------------- launch ------------------------------------------------
extern "C" void kernel_launch(void* const* d_in, const int* in_sizes, int n_in,
                              void* d_out, int out_size) {
    const float* x  = (const float*)d_in[0];
    const void*  ei = d_in[1];
    const float* idv = (const float*)d_in[2];
    const float* W1 = (const float*)d_in[3];
    const float* b1 = (const float*)d_in[4];
    const float* a1 = (const float*)d_in[5];
    const float* W2 = (const float*)d_in[6];
    const float* b2 = (const float*)d_in[7];
    const float* a2 = (const float*)d_in[8];
    float* out = (float*)d_out;

    __nv_bfloat16 *d_axh, *d_axl, *d_h1h, *d_h1l, *d_w1h, *d_w1l, *d_w2h, *d_w2l;
    float *d_h2;
    cudaGetSymbolAddress((void**)&d_axh, g_aggx_hi);
    cudaGetSymbolAddress((void**)&d_axl, g_aggx_lo);
    cudaGetSymbolAddress((void**)&d_h1h, g_h1_hi);
    cudaGetSymbolAddress((void**)&d_h1l, g_h1_lo);
    cudaGetSymbolAddress((void**)&d_w1h, g_wt1_hi);
    cudaGetSymbolAddress((void**)&d_w1l, g_wt1_lo);
    cudaGetSymbolAddress((void**)&d_w2h, g_wt2_hi);
    cudaGetSymbolAddress((void**)&d_w2l, g_wt2_lo);
    cudaGetSymbolAddress((void**)&d_h2, g_h2);

    const int T = 256;
    constexpr int SMEM1 = 2 * (2 * 128 + 2 * 128) * 40 * 2;   // 81920 B
    constexpr int SMEM2 = 2 * (2 * 128 + 2 * 64) * 40 * 2;    // 61440 B

    static bool attr_done = false;
    if (!attr_done) {
        cudaFuncSetAttribute(k_mma<INDIM, HID, 128, true>,
                             cudaFuncAttributeMaxDynamicSharedMemorySize, SMEM1);
        cudaFuncSetAttribute(k_mma<HID, OUTD, 64, false>,
                             cudaFuncAttributeMaxDynamicSharedMemorySize, SMEM2);
        attr_done = true;
    }

    k_detect_zero<<<(NNODES + T - 1) / T, T>>>((const long long*)ei);
    k_deg<<<(NEDGES / 2 + T - 1) / T, T>>>(ei);
    k_scan<<<1, 1024>>>();
    k_csr<<<(NEDGES / 2 + T - 1) / T, T>>>(ei);
    k_prepw<<<(HID * INDIM + OUTD * HID + HID + T - 1) / T, T>>>(W1, W2, idv);

    k_gather1<<<(NNODES * 32 + T - 1) / T, T>>>(x);

    {   // GEMM1: 128x128 tiles
        dim3 grid(HID / 128, (NNODES + 127) / 128);
        k_mma<INDIM, HID, 128, true><<<grid, 256, SMEM1>>>(
            d_axh, d_axl, d_w1h, d_w1l, b1, a1, d_h1h, d_h1l, nullptr, NNODES);
    }
    {   // GEMM2: 128x64 tiles (3 CTAs/SM)
        dim3 grid(OUTD / 64, (NNODES + 127) / 128);
        k_mma<HID, OUTD, 64, false><<<grid, 256, SMEM2>>>(
            d_h1h, d_h1l, d_w2h, d_w2l, nullptr, nullptr, nullptr, nullptr,
            d_h2, NNODES);
    }
    k_gather2<<<(NNODES * 32 + T - 1) / T, T>>>(b2, a2, out);
}

// round 10
// speedup vs baseline: 1.6136x; 1.0770x over previous
#include <cuda_runtime.h>
#include <cuda_bf16.h>
#include <cuda_fp16.h>
#include <cstdint>

// ---------------------------------------------------------------------------
// 2-layer GCN. CSR gather (fp16 rows) + split-bf16 mma.sync GEMMs.
// R10 = R9 + fp16 gather inputs (x pre-converted; h2 emitted fp16) + merged prep.
// ---------------------------------------------------------------------------

static constexpr int NNODES = 50000;
static constexpr int NEDGES = 800000;
static constexpr int INDIM  = 128;
static constexpr int ADDDIM = 8;
static constexpr int HID    = 256;
static constexpr int OUTD   = 128;

// -------------------- device scratch ----------------------------------------
__device__ __align__(16) __half g_xh[(size_t)NNODES * INDIM];          // fp16 copy of x
__device__ __align__(16) __nv_bfloat16 g_aggx_hi[(size_t)NNODES * INDIM];
__device__ __align__(16) __nv_bfloat16 g_aggx_lo[(size_t)NNODES * INDIM];
__device__ __align__(16) __nv_bfloat16 g_h1_hi[(size_t)NNODES * HID];
__device__ __align__(16) __nv_bfloat16 g_h1_lo[(size_t)NNODES * HID];
__device__ __align__(16) __half g_h2[(size_t)NNODES * OUTD];           // fp16 GEMM2 out
__device__ float g_q[NNODES];
__device__ float g_dinv[NNODES];
__device__ int   g_deg[NNODES];
__device__ int   g_off[NNODES + 1];
__device__ int   g_cur[NNODES];
__device__ int   g_src[NEDGES];
__device__ float g_c1[HID];
__device__ __align__(16) __nv_bfloat16 g_wt1_hi[HID * INDIM], g_wt1_lo[HID * INDIM];
__device__ __align__(16) __nv_bfloat16 g_wt2_hi[OUTD * HID],  g_wt2_lo[OUTD * HID];
__device__ int g_is64;

// -------------------- asm helpers -------------------------------------------
__device__ __forceinline__ uint32_t smem_u32(const void* p) {
    return (uint32_t)__cvta_generic_to_shared(p);
}
__device__ __forceinline__ void ldsm_x4(uint32_t r[4], uint32_t addr) {
    asm volatile("ldmatrix.sync.aligned.m8n8.x4.shared.b16 {%0,%1,%2,%3}, [%4];"
                 : "=r"(r[0]), "=r"(r[1]), "=r"(r[2]), "=r"(r[3]) : "r"(addr));
}
__device__ __forceinline__ void mma_bf16(float* c, const uint32_t* a,
                                         uint32_t b0, uint32_t b1) {
    asm volatile(
        "mma.sync.aligned.m16n8k16.row.col.f32.bf16.bf16.f32 "
        "{%0,%1,%2,%3}, {%4,%5,%6,%7}, {%8,%9}, {%0,%1,%2,%3};"
        : "+f"(c[0]), "+f"(c[1]), "+f"(c[2]), "+f"(c[3])
        : "r"(a[0]), "r"(a[1]), "r"(a[2]), "r"(a[3]), "r"(b0), "r"(b1));
}
__device__ __forceinline__ void cp16(uint32_t dst, const void* src, uint32_t sz) {
    asm volatile("cp.async.cg.shared.global [%0], [%1], 16, %2;"
                 :: "r"(dst), "l"(src), "r"(sz) : "memory");
}
__device__ __forceinline__ void cp_commit() {
    asm volatile("cp.async.commit_group;" ::: "memory");
}
template <int N>
__device__ __forceinline__ void cp_wait() {
    asm volatile("cp.async.wait_group %0;" :: "n"(N) : "memory");
}

// -------------------- merged prep: detect + zero deg + x->fp16 + weights ----
__global__ void k_prep0(const float* __restrict__ x, const long long* __restrict__ ei,
                        const float* __restrict__ W1, const float* __restrict__ W2,
                        const float* __restrict__ idv) {
    constexpr int XT = NNODES * INDIM / 4;    // 1,600,000 threads, 4 elems each
    constexpr int N1 = HID * INDIM;
    constexpr int N2 = OUTD * HID;
    int idx = blockIdx.x * blockDim.x + threadIdx.x;

    if (blockIdx.x == 0 && threadIdx.x < 32) {
        bool bad = false;
        for (int j = threadIdx.x; j < 512; j += 32) {
            long long v = ei[j];
            if (v < 0 || v >= NNODES) bad = true;
        }
        unsigned m = __ballot_sync(0xFFFFFFFFu, bad);
        if (threadIdx.x == 0) g_is64 = (m == 0u) ? 1 : 0;
    }

    if (idx < XT) {
        float4 v = __ldg((const float4*)x + idx);
        __half2 p0 = __floats2half2_rn(v.x, v.y);
        __half2 p1 = __floats2half2_rn(v.z, v.w);
        uint2 o;
        o.x = *(uint32_t*)&p0;
        o.y = *(uint32_t*)&p1;
        *((uint2*)g_xh + idx) = o;
    } else if (idx < XT + NNODES) {
        g_deg[idx - XT] = 0;
    } else if (idx < XT + NNODES + N1) {
        int j = idx - XT - NNODES;
        int o = j / INDIM, i = j % INDIM;
        float v = W1[(size_t)i * HID + o];
        __nv_bfloat16 h = __float2bfloat16_rn(v);
        g_wt1_hi[j] = h;
        g_wt1_lo[j] = __float2bfloat16_rn(v - __bfloat162float(h));
    } else if (idx < XT + NNODES + N1 + N2) {
        int j = idx - XT - NNODES - N1;
        int o = j / HID, i = j % HID;
        float v = W2[(size_t)i * OUTD + o];
        __nv_bfloat16 h = __float2bfloat16_rn(v);
        g_wt2_hi[j] = h;
        g_wt2_lo[j] = __float2bfloat16_rn(v - __bfloat162float(h));
    } else if (idx < XT + NNODES + N1 + N2 + HID) {
        int j = idx - XT - NNODES - N1 - N2;
        float s = 0.f;
#pragma unroll
        for (int t = 0; t < ADDDIM; t++) s += idv[t] * W1[(size_t)(INDIM + t) * HID + j];
        g_c1[j] = s;
    }
}

__global__ void k_deg(const void* __restrict__ ei) {
    int i = blockIdx.x * blockDim.x + threadIdx.x;       // pair index
    if (i >= NEDGES / 2) return;
    int d0, d1;
    if (g_is64) {
        longlong2 v = __ldg((const longlong2*)ei + NEDGES / 2 + i);
        d0 = (int)v.x; d1 = (int)v.y;
    } else {
        int2 v = __ldg((const int2*)ei + NEDGES / 2 + i);
        d0 = v.x; d1 = v.y;
    }
    atomicAdd(&g_deg[d0], 1);
    atomicAdd(&g_deg[d1], 1);
}
// exclusive scan (2 elems/thread); also writes dinv
__global__ void k_scan() {
    __shared__ int warpsum[32];
    __shared__ int chunk_total;
    const int t = threadIdx.x;               // 1024
    const int lane = t & 31, wid = t >> 5;
    int run = 0;
    for (int base = 0; base < NNODES; base += 2048) {
        int i0 = base + t * 2, i1 = i0 + 1;
        int v0 = (i0 < NNODES) ? g_deg[i0] : 0;
        int v1 = (i1 < NNODES) ? g_deg[i1] : 0;
        if (i0 < NNODES) g_dinv[i0] = rsqrtf((float)(v0 + 1));
        if (i1 < NNODES) g_dinv[i1] = rsqrtf((float)(v1 + 1));
        int v = v0 + v1;
        int x = v;
#pragma unroll
        for (int o = 1; o < 32; o <<= 1) {
            int y = __shfl_up_sync(0xFFFFFFFFu, x, o);
            if (lane >= o) x += y;
        }
        if (lane == 31) warpsum[wid] = x;
        __syncthreads();
        if (wid == 0) {
            int w = warpsum[lane];
#pragma unroll
            for (int o = 1; o < 32; o <<= 1) {
                int y = __shfl_up_sync(0xFFFFFFFFu, w, o);
                if (lane >= o) w += y;
            }
            warpsum[lane] = w;
            if (lane == 31) chunk_total = w;
        }
        __syncthreads();
        int excl = run + (wid ? warpsum[wid - 1] : 0) + x - v;
        if (i0 < NNODES) { g_off[i0] = excl; g_cur[i0] = excl; }
        if (i1 < NNODES) { g_off[i1] = excl + v0; g_cur[i1] = excl + v0; }
        run += chunk_total;
        __syncthreads();
    }
    if (t == 0) g_off[NNODES] = run;
}
__global__ void k_csr(const void* __restrict__ ei) {
    int i = blockIdx.x * blockDim.x + threadIdx.x;       // pair index
    if (i >= NEDGES / 2) return;
    int s0, s1, d0, d1;
    if (g_is64) {
        longlong2 sv = __ldg((const longlong2*)ei + i);
        longlong2 dv = __ldg((const longlong2*)ei + NEDGES / 2 + i);
        s0 = (int)sv.x; s1 = (int)sv.y; d0 = (int)dv.x; d1 = (int)dv.y;
    } else {
        int2 sv = __ldg((const int2*)ei + i);
        int2 dv = __ldg((const int2*)ei + NEDGES / 2 + i);
        s0 = sv.x; s1 = sv.y; d0 = dv.x; d1 = dv.y;
    }
    int p0 = atomicAdd(&g_cur[d0], 1);
    g_src[p0] = s0;
    int p1 = atomicAdd(&g_cur[d1], 1);
    g_src[p1] = s1;
}

// -------------------- gather1: agg(x fp16) -> bf16 hi/lo + q ----------------
__global__ __launch_bounds__(256) void k_gather1() {
    const int lane = threadIdx.x & 31;
    const int node = (blockIdx.x * blockDim.x + threadIdx.x) >> 5;
    if (node >= NNODES) return;
    const float dv = g_dinv[node];
    const int e0 = g_off[node], e1 = g_off[node + 1];
    float4 acc = make_float4(0.f, 0.f, 0.f, 0.f);
    float q = 0.f;

    auto rowfma = [&](int s, float w) {
        uint2 hv = __ldg((const uint2*)(g_xh + (size_t)s * INDIM) + lane);
        __half2 p0 = *(__half2*)&hv.x;
        __half2 p1 = *(__half2*)&hv.y;
        float2 f0 = __half22float2(p0);
        float2 f1 = __half22float2(p1);
        acc.x += f0.x * w; acc.y += f0.y * w;
        acc.z += f1.x * w; acc.w += f1.y * w;
    };

    int e = e0;
    for (; e + 4 <= e1; e += 4) {
        int s0 = __ldg(&g_src[e]),     s1 = __ldg(&g_src[e + 1]);
        int s2 = __ldg(&g_src[e + 2]), s3 = __ldg(&g_src[e + 3]);
        float w0 = __ldg(&g_dinv[s0]) * dv, w1 = __ldg(&g_dinv[s1]) * dv;
        float w2 = __ldg(&g_dinv[s2]) * dv, w3 = __ldg(&g_dinv[s3]) * dv;
        q += (w0 + w1) + (w2 + w3);
        rowfma(s0, w0); rowfma(s1, w1); rowfma(s2, w2); rowfma(s3, w3);
    }
    for (; e < e1; e++) {
        int s0 = __ldg(&g_src[e]);
        float w0 = __ldg(&g_dinv[s0]) * dv;
        q += w0;
        rowfma(s0, w0);
    }
    {
        float w = dv * dv;
        q += w;
        rowfma(node, w);
    }
    float vals[4] = {acc.x, acc.y, acc.z, acc.w};
    uint32_t hp[2], lp[2];
#pragma unroll
    for (int p = 0; p < 2; p++) {
        __nv_bfloat16 h0 = __float2bfloat16_rn(vals[p * 2]);
        __nv_bfloat16 h1 = __float2bfloat16_rn(vals[p * 2 + 1]);
        __nv_bfloat16 l0 = __float2bfloat16_rn(vals[p * 2] - __bfloat162float(h0));
        __nv_bfloat16 l1 = __float2bfloat16_rn(vals[p * 2 + 1] - __bfloat162float(h1));
        hp[p] = (uint32_t)__bfloat16_as_ushort(h0) | ((uint32_t)__bfloat16_as_ushort(h1) << 16);
        lp[p] = (uint32_t)__bfloat16_as_ushort(l0) | ((uint32_t)__bfloat16_as_ushort(l1) << 16);
    }
    size_t base = (size_t)node * INDIM + lane * 4;
    *(uint2*)&g_aggx_hi[base] = make_uint2(hp[0], hp[1]);
    *(uint2*)&g_aggx_lo[base] = make_uint2(lp[0], lp[1]);
    if (lane == 0) g_q[node] = q;
}

// -------------------- double-buffered split-bf16 GEMM -----------------------
// CTA tile: 128 rows x BN cols. 8 warps in 4x2. BK=32.
// L1: epilogue prelu(D+q*c1+bias) -> bf16 hi/lo. else: fp16 out (g_h2).
template <int K, int NTOT, int BN, bool L1>
__global__ __launch_bounds__(256) void k_mma(
    const __nv_bfloat16* __restrict__ Ahi, const __nv_bfloat16* __restrict__ Alo,
    const __nv_bfloat16* __restrict__ Bhi, const __nv_bfloat16* __restrict__ Blo,
    const float* __restrict__ bias, const float* __restrict__ slope,
    __nv_bfloat16* __restrict__ OutHi, __nv_bfloat16* __restrict__ OutLo,
    __half* __restrict__ OutH, int M) {
    constexpr int BK = 32, SA = 40;
    constexpr int NSEG = K / BK;
    constexpr int TA = 128 * SA * 2;
    constexpr int TB = BN * SA * 2;
    constexpr int BUF = 2 * TA + 2 * TB;
    constexpr int NQ = BN / 32;

    extern __shared__ __align__(16) __nv_bfloat16 smem[];

    const int t = threadIdx.x;
    const int lane = t & 31, warp = t >> 5;
    const int wm0 = (warp >> 1) * 32;
    const int wn0 = (warp & 1) * (BN / 2);
    const int row0 = blockIdx.y * 128;
    const int n0 = blockIdx.x * BN;

    auto load_seg = [&](int seg, int b) {
        const int k0 = seg * BK;
        const uint32_t sbase = smem_u32(smem) + (uint32_t)b * BUF;
#pragma unroll
        for (int tl = 0; tl < 2; tl++) {
            const __nv_bfloat16* G = tl ? Alo : Ahi;
            uint32_t tbase = sbase + tl * TA;
#pragma unroll
            for (int c = t; c < 512; c += 256) {
                int r = c >> 2, ch = c & 3;
                int gr = row0 + r;
                uint32_t ok = (gr < M) ? 16u : 0u;
                cp16(tbase + r * (SA * 2) + ch * 16,
                     G + (size_t)gr * K + k0 + ch * 8, ok);
            }
        }
#pragma unroll
        for (int tl = 0; tl < 2; tl++) {
            const __nv_bfloat16* G = tl ? Blo : Bhi;
            uint32_t tbase = sbase + 2 * TA + tl * TB;
#pragma unroll
            for (int c = t; c < BN * 4; c += 256) {
                int r = c >> 2, ch = c & 3;
                cp16(tbase + r * (SA * 2) + ch * 16,
                     G + (size_t)(n0 + r) * K + k0 + ch * 8, 16u);
            }
        }
        cp_commit();
    };

    float acc[2][2 * NQ][4] = {};

    load_seg(0, 0);
    for (int s = 0; s < NSEG; s++) {
        const int b = s & 1;
        if (s + 1 < NSEG) load_seg(s + 1, b ^ 1);
        if (s + 1 < NSEG) cp_wait<1>(); else cp_wait<0>();
        __syncthreads();

        const uint32_t sb = smem_u32(smem) + (uint32_t)b * BUF;
        const uint32_t aHi = sb, aLo = sb + TA;
        const uint32_t bHi = sb + 2 * TA, bLo = sb + 2 * TA + TB;

#pragma unroll
        for (int ph = 0; ph < 3; ph++) {
            const uint32_t at = (ph == 1) ? aLo : aHi;
            const uint32_t bt = (ph == 2) ? bLo : bHi;
#pragma unroll
            for (int kh = 0; kh < 2; kh++) {
                uint32_t af[2][4], bf[NQ][4];
#pragma unroll
                for (int mi = 0; mi < 2; mi++) {
                    uint32_t addr = at +
                        ((wm0 + mi * 16 + (lane & 15)) * SA + kh * 16 + (lane >> 4) * 8) * 2;
                    ldsm_x4(af[mi], addr);
                }
#pragma unroll
                for (int nq = 0; nq < NQ; nq++) {
                    uint32_t addr = bt +
                        ((wn0 + nq * 16 + (lane & 7) + ((lane >> 4) & 1) * 8) * SA +
                         kh * 16 + ((lane >> 3) & 1) * 8) * 2;
                    ldsm_x4(bf[nq], addr);
                }
#pragma unroll
                for (int mi = 0; mi < 2; mi++)
#pragma unroll
                    for (int nq = 0; nq < NQ; nq++) {
                        mma_bf16(acc[mi][nq * 2],     af[mi], bf[nq][0], bf[nq][1]);
                        mma_bf16(acc[mi][nq * 2 + 1], af[mi], bf[nq][2], bf[nq][3]);
                    }
            }
        }
        __syncthreads();
    }

    // epilogue
    float qv[2][2];
    if (L1) {
#pragma unroll
        for (int mi = 0; mi < 2; mi++) {
            int r0 = row0 + wm0 + mi * 16 + (lane >> 2);
            qv[mi][0] = (r0 < M) ? __ldg(&g_q[r0]) : 0.f;
            qv[mi][1] = (r0 + 8 < M) ? __ldg(&g_q[r0 + 8]) : 0.f;
        }
    }
#pragma unroll
    for (int mi = 0; mi < 2; mi++) {
        int r0 = row0 + wm0 + mi * 16 + (lane >> 2);
#pragma unroll
        for (int nt = 0; nt < 2 * NQ; nt++) {
            int c0 = n0 + wn0 + nt * 8 + (lane & 3) * 2;
            if (L1) {
                float cc0 = __ldg(&g_c1[c0]),   cc1 = __ldg(&g_c1[c0 + 1]);
                float bb0 = __ldg(&bias[c0]),   bb1 = __ldg(&bias[c0 + 1]);
                float ss0 = __ldg(&slope[c0]),  ss1 = __ldg(&slope[c0 + 1]);
#pragma unroll
                for (int h = 0; h < 2; h++) {
                    int r = r0 + h * 8;
                    if (r >= M) continue;
                    float v0 = acc[mi][nt][h * 2]     + qv[mi][h] * cc0 + bb0;
                    float v1 = acc[mi][nt][h * 2 + 1] + qv[mi][h] * cc1 + bb1;
                    v0 = v0 >= 0.f ? v0 : ss0 * v0;
                    v1 = v1 >= 0.f ? v1 : ss1 * v1;
                    __nv_bfloat16 h0 = __float2bfloat16_rn(v0);
                    __nv_bfloat16 h1 = __float2bfloat16_rn(v1);
                    __nv_bfloat16 l0 = __float2bfloat16_rn(v0 - __bfloat162float(h0));
                    __nv_bfloat16 l1 = __float2bfloat16_rn(v1 - __bfloat162float(h1));
                    size_t o = (size_t)r * NTOT + c0;
                    *(uint32_t*)(OutHi + o) = (uint32_t)__bfloat16_as_ushort(h0) |
                                              ((uint32_t)__bfloat16_as_ushort(h1) << 16);
                    *(uint32_t*)(OutLo + o) = (uint32_t)__bfloat16_as_ushort(l0) |
                                              ((uint32_t)__bfloat16_as_ushort(l1) << 16);
                }
            } else {
#pragma unroll
                for (int h = 0; h < 2; h++) {
                    int r = r0 + h * 8;
                    if (r >= M) continue;
                    __half2 hh = __floats2half2_rn(acc[mi][nt][h * 2],
                                                   acc[mi][nt][h * 2 + 1]);
                    *(uint32_t*)(OutH + (size_t)r * NTOT + c0) = *(uint32_t*)&hh;
                }
            }
        }
    }
}

// -------------------- gather2: fp16 h2 rows, fused bias+prelu ---------------
__global__ __launch_bounds__(256) void k_gather2(const float* __restrict__ bias,
                                                 const float* __restrict__ slope,
                                                 float* __restrict__ out) {
    const int lane = threadIdx.x & 31;
    const int node = (blockIdx.x * blockDim.x + threadIdx.x) >> 5;
    if (node >= NNODES) return;
    const float dv = g_dinv[node];
    const int e0 = g_off[node], e1 = g_off[node + 1];
    float4 acc = make_float4(0.f, 0.f, 0.f, 0.f);

    auto rowfma = [&](int s, float w) {
        uint2 hv = __ldg((const uint2*)(g_h2 + (size_t)s * OUTD) + lane);
        __half2 p0 = *(__half2*)&hv.x;
        __half2 p1 = *(__half2*)&hv.y;
        float2 f0 = __half22float2(p0);
        float2 f1 = __half22float2(p1);
        acc.x += f0.x * w; acc.y += f0.y * w;
        acc.z += f1.x * w; acc.w += f1.y * w;
    };

    int e = e0;
    for (; e + 4 <= e1; e += 4) {
        int s0 = __ldg(&g_src[e]),     s1 = __ldg(&g_src[e + 1]);
        int s2 = __ldg(&g_src[e + 2]), s3 = __ldg(&g_src[e + 3]);
        float w0 = __ldg(&g_dinv[s0]) * dv, w1 = __ldg(&g_dinv[s1]) * dv;
        float w2 = __ldg(&g_dinv[s2]) * dv, w3 = __ldg(&g_dinv[s3]) * dv;
        rowfma(s0, w0); rowfma(s1, w1); rowfma(s2, w2); rowfma(s3, w3);
    }
    for (; e < e1; e++) {
        int s0 = __ldg(&g_src[e]);
        float w0 = __ldg(&g_dinv[s0]) * dv;
        rowfma(s0, w0);
    }
    rowfma(node, dv * dv);

    float4 B = *(const float4*)&bias[lane * 4];
    float4 S = *(const float4*)&slope[lane * 4];
    float r0 = acc.x + B.x, r1 = acc.y + B.y, r2 = acc.z + B.z, r3 = acc.w + B.w;
    float4 o;
    o.x = r0 >= 0.f ? r0 : S.x * r0;
    o.y = r1 >= 0.f ? r1 : S.y * r1;
    o.z = r2 >= 0.f ? r2 : S.z * r2;
    o.w = r3 >= 0.f ? r3 : S.w * r3;
    *(float4*)&out[(size_t)node * OUTD + lane * 4] = o;
}

// -------------------- launch ------------------------------------------------
extern "C" void kernel_launch(void* const* d_in, const int* in_sizes, int n_in,
                              void* d_out, int out_size) {
    const float* x  = (const float*)d_in[0];
    const void*  ei = d_in[1];
    const float* idv = (const float*)d_in[2];
    const float* W1 = (const float*)d_in[3];
    const float* b1 = (const float*)d_in[4];
    const float* a1 = (const float*)d_in[5];
    const float* W2 = (const float*)d_in[6];
    const float* b2 = (const float*)d_in[7];
    const float* a2 = (const float*)d_in[8];
    float* out = (float*)d_out;

    __nv_bfloat16 *d_axh, *d_axl, *d_h1h, *d_h1l, *d_w1h, *d_w1l, *d_w2h, *d_w2l;
    __half *d_h2;
    cudaGetSymbolAddress((void**)&d_axh, g_aggx_hi);
    cudaGetSymbolAddress((void**)&d_axl, g_aggx_lo);
    cudaGetSymbolAddress((void**)&d_h1h, g_h1_hi);
    cudaGetSymbolAddress((void**)&d_h1l, g_h1_lo);
    cudaGetSymbolAddress((void**)&d_w1h, g_wt1_hi);
    cudaGetSymbolAddress((void**)&d_w1l, g_wt1_lo);
    cudaGetSymbolAddress((void**)&d_w2h, g_wt2_hi);
    cudaGetSymbolAddress((void**)&d_w2l, g_wt2_lo);
    cudaGetSymbolAddress((void**)&d_h2, g_h2);

    const int T = 256;
    constexpr int SMEM1 = 2 * (2 * 128 + 2 * 128) * 40 * 2;   // 81920 B
    constexpr int SMEM2 = 2 * (2 * 128 + 2 * 64) * 40 * 2;    // 61440 B

    static bool attr_done = false;
    if (!attr_done) {
        cudaFuncSetAttribute(k_mma<INDIM, HID, 128, true>,
                             cudaFuncAttributeMaxDynamicSharedMemorySize, SMEM1);
        cudaFuncSetAttribute(k_mma<HID, OUTD, 64, false>,
                             cudaFuncAttributeMaxDynamicSharedMemorySize, SMEM2);
        attr_done = true;
    }

    // merged prep: detect + zero deg + x->fp16 + weight split + c1
    {
        constexpr int TOT = NNODES * INDIM / 4 + NNODES +
                            HID * INDIM + OUTD * HID + HID;
        k_prep0<<<(TOT + T - 1) / T, T>>>(x, (const long long*)ei, W1, W2, idv);
    }
    k_deg<<<(NEDGES / 2 + T - 1) / T, T>>>(ei);
    k_scan<<<1, 1024>>>();
    k_csr<<<(NEDGES / 2 + T - 1) / T, T>>>(ei);

    k_gather1<<<(NNODES * 32 + T - 1) / T, T>>>();

    {   // GEMM1: 128x128 tiles
        dim3 grid(HID / 128, (NNODES + 127) / 128);
        k_mma<INDIM, HID, 128, true><<<grid, 256, SMEM1>>>(
            d_axh, d_axl, d_w1h, d_w1l, b1, a1, d_h1h, d_h1l, nullptr, NNODES);
    }
    {   // GEMM2: 128x64 tiles (3 CTAs/SM) -> fp16 h2
        dim3 grid(OUTD / 64, (NNODES + 127) / 128);
        k_mma<HID, OUTD, 64, false><<<grid, 256, SMEM2>>>(
            d_h1h, d_h1l, d_w2h, d_w2l, nullptr, nullptr, nullptr, nullptr,
            d_h2, NNODES);
    }
    k_gather2<<<(NNODES * 32 + T - 1) / T, T>>>(b2, a2, out);
}